// round 1
// baseline (speedup 1.0000x reference)
#include <cuda_runtime.h>
#include <cstdint>
#include <cstddef>

// Problem constants
#define NN 10000
#define KK 16
#define MEAN_NODES 625.0f

// Main-kernel tiling
#define JT 2560          // columns (j) per shared-memory Y tile
#define PITCH 20         // floats per Y row in smem (pad 16->20: conflict-free LDS.128)
#define THREADS 512      // 16 warps
#define TI 4             // rows per warp (per row-group)
#define RG 2             // row-groups per block
#define ROWS_PER_BLOCK (16 * TI * RG)              // 128
#define NBLK_ROWS ((NN + ROWS_PER_BLOCK - 1) / ROWS_PER_BLOCK)  // 79
#define NBLK_J ((NN + JT - 1) / JT)                // 4
#define SMEM_BYTES (JT * PITCH * 4)                // 204800 B

#define PBLOCKS 40       // partial-reduction blocks for gamma/colsum

// Device-global scratch (no allocations allowed)
__device__ double g_cut;
__device__ float  g_invg[KK];
__device__ float  g_ep;
__device__ float  g_part[PBLOCKS * 32];

// ---- packed f32x2 helpers (Blackwell FFMA2) ----
__device__ __forceinline__ unsigned long long ffma2(unsigned long long a,
                                                    unsigned long long b,
                                                    unsigned long long c) {
    unsigned long long d;
    asm("fma.rn.f32x2 %0, %1, %2, %3;" : "=l"(d) : "l"(a), "l"(b), "l"(c));
    return d;
}
__device__ __forceinline__ unsigned long long pack2(float x, float y) {
    unsigned long long d;
    asm("mov.b64 %0, {%1, %2};" : "=l"(d) : "f"(x), "f"(y));
    return d;
}
__device__ __forceinline__ float2 unpack2(unsigned long long v) {
    float2 r;
    asm("mov.b64 {%0, %1}, %2;" : "=f"(r.x), "=f"(r.y) : "l"(v));
    return r;
}

// ============================================================
// Kernel 1: per-block partials of gamma[k] = sum_i Y[i,k]*deg[i]
//           and colsum[k] = sum_i Y[i,k]
// ============================================================
__global__ void k_partial(const float* __restrict__ Y,
                          const float* __restrict__ deg) {
    int i = blockIdx.x * 256 + threadIdx.x;
    float g[KK], c[KK];
#pragma unroll
    for (int k = 0; k < KK; k++) { g[k] = 0.f; c[k] = 0.f; }

    if (i < NN) {
        float d = deg[i];
        const float4* yr = (const float4*)(Y + (size_t)i * KK);
#pragma unroll
        for (int q = 0; q < 4; q++) {
            float4 v = yr[q];
            c[q * 4 + 0] = v.x; c[q * 4 + 1] = v.y;
            c[q * 4 + 2] = v.z; c[q * 4 + 3] = v.w;
            g[q * 4 + 0] = v.x * d; g[q * 4 + 1] = v.y * d;
            g[q * 4 + 2] = v.z * d; g[q * 4 + 3] = v.w * d;
        }
    }
    // warp-level reduce all 32 values
#pragma unroll
    for (int k = 0; k < KK; k++) {
#pragma unroll
        for (int o = 16; o; o >>= 1) {
            g[k] += __shfl_xor_sync(0xffffffffu, g[k], o);
            c[k] += __shfl_xor_sync(0xffffffffu, c[k], o);
        }
    }
    __shared__ float red[8][32];
    int warp = threadIdx.x >> 5, lane = threadIdx.x & 31;
    if (lane == 0) {
#pragma unroll
        for (int k = 0; k < KK; k++) {
            red[warp][k]      = g[k];
            red[warp][16 + k] = c[k];
        }
    }
    __syncthreads();
    if (threadIdx.x < 32) {
        float s = 0.f;
#pragma unroll
        for (int w = 0; w < 8; w++) s += red[w][threadIdx.x];
        g_part[blockIdx.x * 32 + threadIdx.x] = s;
    }
}

// ============================================================
// Kernel 2: finalize gamma -> 1/gamma, error_partition; zero g_cut
// ============================================================
__global__ void k_prep() {
    int t = threadIdx.x;  // 32 threads, 1 warp
    float s = 0.f;
    for (int b = 0; b < PBLOCKS; b++) s += g_part[b * 32 + t];
    __shared__ float sh[32];
    sh[t] = s;
    __syncwarp();
    if (t < KK) g_invg[t] = 1.0f / s;
    if (t == 0) {
        float e = 0.f;
#pragma unroll
        for (int k = 0; k < KK; k++) {
            float d = sh[16 + k] - MEAN_NODES;
            e += d * d;
        }
        g_ep  = e;
        g_cut = 0.0;
    }
}

// ============================================================
// Kernel 3: main fused pass over A
//   per (i, j): rowsum_i += A_ij; B_i[k] += A_ij * Y[j,k]
//   finalize: part += s_i * rowsum_i - dot(Yn_i, B_i)
// ============================================================
extern __shared__ float sY[];

__global__ void __launch_bounds__(THREADS, 1)
k_main(const float* __restrict__ A, const float* __restrict__ Y) {
    const int jt = blockIdx.x;
    const int rb = blockIdx.y;
    const int j0 = jt * JT;

    // cooperative Y tile load: Y[j0 .. j0+JT) -> sY, pitch 20, zero-fill tail
    for (int idx = threadIdx.x; idx < JT * 4; idx += THREADS) {
        int r = idx >> 2, c = idx & 3;
        int j = j0 + r;
        float4 v = make_float4(0.f, 0.f, 0.f, 0.f);
        if (j < NN) v = *(const float4*)(Y + (size_t)j * KK + c * 4);
        *(float4*)(sY + r * PITCH + c * 4) = v;
    }
    __syncthreads();

    const int warp = threadIdx.x >> 5;
    const int lane = threadIdx.x & 31;
    const int jlim = NN - j0;  // local columns that are valid
    float part = 0.0f;

#pragma unroll 1
    for (int rg = 0; rg < RG; rg++) {
        const int i0 = rb * ROWS_PER_BLOCK + rg * (16 * TI) + warp * TI;

        unsigned long long acc[TI][8];
        float rowsum[TI];
        bool valid[TI];
        const float* aptr[TI];
#pragma unroll
        for (int r = 0; r < TI; r++) {
            rowsum[r] = 0.f;
            valid[r]  = (i0 + r) < NN;
            aptr[r]   = A + (size_t)(i0 + r) * NN + j0;
#pragma unroll
            for (int p = 0; p < 8; p++) acc[r][p] = 0ULL;
        }

#pragma unroll 2
        for (int step = 0; step < JT / 32; step++) {
            const int jj  = step * 32 + lane;     // local column
            const bool jok = jj < jlim;

            // A values for TI rows (coalesced, streaming)
            float a[TI];
#pragma unroll
            for (int r = 0; r < TI; r++)
                a[r] = (jok && valid[r]) ? __ldcs(aptr[r] + jj) : 0.f;

            // Y[j, 0..15] as 8 packed f32x2 from smem (conflict-free)
            const ulonglong2* yp = (const ulonglong2*)(sY + jj * PITCH);
            ulonglong2 y01 = yp[0], y23 = yp[1], y45 = yp[2], y67 = yp[3];

#pragma unroll
            for (int r = 0; r < TI; r++) {
                rowsum[r] += a[r];
                unsigned long long ap = pack2(a[r], a[r]);
                acc[r][0] = ffma2(ap, y01.x, acc[r][0]);
                acc[r][1] = ffma2(ap, y01.y, acc[r][1]);
                acc[r][2] = ffma2(ap, y23.x, acc[r][2]);
                acc[r][3] = ffma2(ap, y23.y, acc[r][3]);
                acc[r][4] = ffma2(ap, y45.x, acc[r][4]);
                acc[r][5] = ffma2(ap, y45.y, acc[r][5]);
                acc[r][6] = ffma2(ap, y67.x, acc[r][6]);
                acc[r][7] = ffma2(ap, y67.y, acc[r][7]);
            }
        }

        // finalize this row-group
        float iv[KK];
#pragma unroll
        for (int k = 0; k < KK; k++) iv[k] = g_invg[k];

#pragma unroll
        for (int r = 0; r < TI; r++) {
            if (!valid[r]) continue;
            const float* yi = Y + (size_t)(i0 + r) * KK;
            float yn[KK], s = 0.f;
#pragma unroll
            for (int k = 0; k < KK; k++) {
                yn[k] = yi[k] * iv[k];
                s += yn[k];
            }
            float dot = 0.f;
#pragma unroll
            for (int p = 0; p < 8; p++) {
                float2 u = unpack2(acc[r][p]);
                dot += yn[2 * p] * u.x + yn[2 * p + 1] * u.y;
            }
            part += s * rowsum[r] - dot;
        }
    }

    // warp reduce, one double atomic per warp
#pragma unroll
    for (int o = 16; o; o >>= 1) part += __shfl_xor_sync(0xffffffffu, part, o);
    if (lane == 0) atomicAdd(&g_cut, (double)part);
}

// ============================================================
// Kernel 4: write scalar output
// ============================================================
__global__ void k_out(float* __restrict__ out) {
    out[0] = (float)(g_cut + (double)g_ep);
}

extern "C" void kernel_launch(void* const* d_in, const int* in_sizes, int n_in,
                              void* d_out, int out_size) {
    const float* Y   = (const float*)d_in[0];   // [N, K]
    const float* A   = (const float*)d_in[1];   // [N, N]
    const float* deg = (const float*)d_in[2];   // [N, 1]
    float* out = (float*)d_out;

    cudaFuncSetAttribute(k_main, cudaFuncAttributeMaxDynamicSharedMemorySize,
                         SMEM_BYTES);

    k_partial<<<PBLOCKS, 256>>>(Y, deg);
    k_prep<<<1, 32>>>();
    dim3 grid(NBLK_J, NBLK_ROWS);
    k_main<<<grid, THREADS, SMEM_BYTES>>>(A, Y);
    k_out<<<1, 1>>>(out);
}

// round 2
// speedup vs baseline: 1.3447x; 1.3447x over previous
#include <cuda_runtime.h>
#include <cstdint>
#include <cstddef>

// Problem constants
#define NN 10000
#define KK 16
#define MEAN_NODES 625.0f

// Main-kernel tiling: exactly one wave of 148 blocks (4 j-tiles x 37 row-blocks)
#define JT 2560          // columns per shared-memory W tile
#define PITCH 20         // floats per row in smem (pad 16->20: conflict-free LDS.128)
#define THREADS 512      // 16 warps
#define TI 4             // rows per warp per row-group pass
#define ROWS_PER_PASS (16 * TI)     // 64
#define RG 5                        // passes: 5*64 = 320 >= 272
#define ROWS_PER_BLOCK 272          // 37 * 272 = 10064 >= 10000
#define NBLK_ROWS 37
#define NBLK_J 4
#define STEPS (JT / 32)             // 80
#define SMEM_BYTES (JT * PITCH * 4) // 204800 B

#define PBLOCKS 40

// Device-global scratch
__device__ double g_cut;
__device__ float  g_invg[KK];
__device__ float  g_ep;
__device__ float  g_part[PBLOCKS * 32];

// ---- packed f32x2 helpers (Blackwell FFMA2) ----
__device__ __forceinline__ unsigned long long ffma2(unsigned long long a,
                                                    unsigned long long b,
                                                    unsigned long long c) {
    unsigned long long d;
    asm("fma.rn.f32x2 %0, %1, %2, %3;" : "=l"(d) : "l"(a), "l"(b), "l"(c));
    return d;
}
__device__ __forceinline__ unsigned long long pack2(float x, float y) {
    unsigned long long d;
    asm("mov.b64 %0, {%1, %2};" : "=l"(d) : "f"(x), "f"(y));
    return d;
}
__device__ __forceinline__ float2 unpack2(unsigned long long v) {
    float2 r;
    asm("mov.b64 {%0, %1}, %2;" : "=f"(r.x), "=f"(r.y) : "l"(v));
    return r;
}

// ============================================================
// Kernel 1: per-block partials of gamma[k] and colsum[k]
// ============================================================
__global__ void k_partial(const float* __restrict__ Y,
                          const float* __restrict__ deg) {
    int i = blockIdx.x * 256 + threadIdx.x;
    float g[KK], c[KK];
#pragma unroll
    for (int k = 0; k < KK; k++) { g[k] = 0.f; c[k] = 0.f; }

    if (i < NN) {
        float d = deg[i];
        const float4* yr = (const float4*)(Y + (size_t)i * KK);
#pragma unroll
        for (int q = 0; q < 4; q++) {
            float4 v = yr[q];
            c[q * 4 + 0] = v.x; c[q * 4 + 1] = v.y;
            c[q * 4 + 2] = v.z; c[q * 4 + 3] = v.w;
            g[q * 4 + 0] = v.x * d; g[q * 4 + 1] = v.y * d;
            g[q * 4 + 2] = v.z * d; g[q * 4 + 3] = v.w * d;
        }
    }
#pragma unroll
    for (int k = 0; k < KK; k++) {
#pragma unroll
        for (int o = 16; o; o >>= 1) {
            g[k] += __shfl_xor_sync(0xffffffffu, g[k], o);
            c[k] += __shfl_xor_sync(0xffffffffu, c[k], o);
        }
    }
    __shared__ float red[8][32];
    int warp = threadIdx.x >> 5, lane = threadIdx.x & 31;
    if (lane == 0) {
#pragma unroll
        for (int k = 0; k < KK; k++) {
            red[warp][k]      = g[k];
            red[warp][16 + k] = c[k];
        }
    }
    __syncthreads();
    if (threadIdx.x < 32) {
        float s = 0.f;
#pragma unroll
        for (int w = 0; w < 8; w++) s += red[w][threadIdx.x];
        g_part[blockIdx.x * 32 + threadIdx.x] = s;
    }
}

// ============================================================
// Kernel 2: finalize gamma -> 1/gamma, error_partition; zero g_cut
// ============================================================
__global__ void k_prep() {
    int t = threadIdx.x;  // 32 threads
    float s = 0.f;
    for (int b = 0; b < PBLOCKS; b++) s += g_part[b * 32 + t];
    __shared__ float sh[32];
    sh[t] = s;
    __syncwarp();
    if (t < KK) g_invg[t] = 1.0f / s;
    if (t == 0) {
        float e = 0.f;
#pragma unroll
        for (int k = 0; k < KK; k++) {
            float d = sh[16 + k] - MEAN_NODES;
            e += d * d;
        }
        g_ep  = e;
        g_cut = 0.0;
    }
}

// ============================================================
// Kernel 3: main fused pass over A
//   W tile holds w_jk = 1 - Y[j,k]. Per (i,j): Wacc_i[k] += A_ij * w_jk
//   finalize: part += dot(Yn_i, Wacc_i)
// ============================================================
extern __shared__ float sW[];

__global__ void __launch_bounds__(THREADS, 1)
k_main(const float* __restrict__ A, const float* __restrict__ Y) {
    const int jt = blockIdx.x;
    const int rb = blockIdx.y;
    const int j0 = jt * JT;
    const int jlim = NN - j0;  // valid local columns (may be < JT on last tile)

    // Cooperative tile load: w = 1 - Y[j0..j0+JT), pitch 20, zero-fill tail
    for (int idx = threadIdx.x; idx < JT * 4; idx += THREADS) {
        int r = idx >> 2, c = idx & 3;
        int j = j0 + r;
        float4 v = make_float4(0.f, 0.f, 0.f, 0.f);
        if (j < NN) {
            float4 y = *(const float4*)(Y + (size_t)j * KK + c * 4);
            v = make_float4(1.f - y.x, 1.f - y.y, 1.f - y.z, 1.f - y.w);
        }
        *(float4*)(sW + r * PITCH + c * 4) = v;
    }
    __syncthreads();

    const int warp = threadIdx.x >> 5;
    const int lane = threadIdx.x & 31;
    float part = 0.0f;

#pragma unroll 1
    for (int rg = 0; rg < RG; rg++) {
        const int li = rg * ROWS_PER_PASS + warp * TI;  // local row in block
        const int i0 = rb * ROWS_PER_BLOCK + li;        // global row
        if (li >= ROWS_PER_BLOCK || i0 >= NN) continue; // warp-uniform skip

        bool rvalid[TI];
        const float* aptr[TI];
        unsigned long long acc[TI][8];
#pragma unroll
        for (int r = 0; r < TI; r++) {
            rvalid[r] = (li + r) < ROWS_PER_BLOCK && (i0 + r) < NN;
            aptr[r]   = A + (size_t)(i0 + r) * NN + j0;
#pragma unroll
            for (int p = 0; p < 8; p++) acc[r][p] = 0ULL;
        }

        // software pipeline: prefetch step 0
        float a[TI];
        {
            const bool jok = lane < jlim;
#pragma unroll
            for (int r = 0; r < TI; r++)
                a[r] = (jok && rvalid[r]) ? __ldcs(aptr[r] + lane) : 0.f;
        }

#pragma unroll 2
        for (int step = 0; step < STEPS; step++) {
            // prefetch next step's A values
            float an[TI];
            const int  jn  = (step + 1) * 32 + lane;
            const bool jokn = (step + 1 < STEPS) && (jn < jlim);
#pragma unroll
            for (int r = 0; r < TI; r++)
                an[r] = (jokn && rvalid[r]) ? __ldcs(aptr[r] + jn) : 0.f;

            // W[j, 0..15] as 8 packed f32x2 from smem (conflict-free, pitch 20)
            const int jj = step * 32 + lane;
            const ulonglong2* yp = (const ulonglong2*)(sW + jj * PITCH);
            ulonglong2 y01 = yp[0], y23 = yp[1], y45 = yp[2], y67 = yp[3];

#pragma unroll
            for (int r = 0; r < TI; r++) {
                unsigned long long ap = pack2(a[r], a[r]);
                acc[r][0] = ffma2(ap, y01.x, acc[r][0]);
                acc[r][1] = ffma2(ap, y01.y, acc[r][1]);
                acc[r][2] = ffma2(ap, y23.x, acc[r][2]);
                acc[r][3] = ffma2(ap, y23.y, acc[r][3]);
                acc[r][4] = ffma2(ap, y45.x, acc[r][4]);
                acc[r][5] = ffma2(ap, y45.y, acc[r][5]);
                acc[r][6] = ffma2(ap, y67.x, acc[r][6]);
                acc[r][7] = ffma2(ap, y67.y, acc[r][7]);
            }
#pragma unroll
            for (int r = 0; r < TI; r++) a[r] = an[r];
        }

        // finalize this row-group
        float iv[KK];
#pragma unroll
        for (int k = 0; k < KK; k++) iv[k] = g_invg[k];

#pragma unroll
        for (int r = 0; r < TI; r++) {
            if (!rvalid[r]) continue;
            const float* yi = Y + (size_t)(i0 + r) * KK;
            float dot = 0.f;
#pragma unroll
            for (int p = 0; p < 8; p++) {
                float2 u = unpack2(acc[r][p]);
                dot += (yi[2 * p]     * iv[2 * p])     * u.x
                     + (yi[2 * p + 1] * iv[2 * p + 1]) * u.y;
            }
            part += dot;
        }
    }

    // warp reduce, one double atomic per warp
#pragma unroll
    for (int o = 16; o; o >>= 1) part += __shfl_xor_sync(0xffffffffu, part, o);
    if (lane == 0) atomicAdd(&g_cut, (double)part);
}

// ============================================================
// Kernel 4: write scalar output
// ============================================================
__global__ void k_out(float* __restrict__ out) {
    out[0] = (float)(g_cut + (double)g_ep);
}

extern "C" void kernel_launch(void* const* d_in, const int* in_sizes, int n_in,
                              void* d_out, int out_size) {
    const float* Y   = (const float*)d_in[0];   // [N, K]
    const float* A   = (const float*)d_in[1];   // [N, N]
    const float* deg = (const float*)d_in[2];   // [N, 1]
    float* out = (float*)d_out;

    cudaFuncSetAttribute(k_main, cudaFuncAttributeMaxDynamicSharedMemorySize,
                         SMEM_BYTES);

    k_partial<<<PBLOCKS, 256>>>(Y, deg);
    k_prep<<<1, 32>>>();
    dim3 grid(NBLK_J, NBLK_ROWS);
    k_main<<<grid, THREADS, SMEM_BYTES>>>(A, Y);
    k_out<<<1, 1>>>(out);
}

// round 3
// speedup vs baseline: 1.7537x; 1.3041x over previous
#include <cuda_runtime.h>
#include <cstdint>
#include <cstddef>

// Problem constants
#define NN 10000
#define KK 16
#define MEAN_NODES 625.0f

// Main-kernel tiling: exactly one wave of 148 blocks (4 j-tiles x 37 row-blocks)
#define JT 2560          // columns per shared-memory W tile
#define PITCH 20         // floats/row in smem: conflict-free LDS.128 at lane-stride-1-row
#define THREADS 512      // 16 warps
#define TI 4             // rows per warp per pass
#define ROWS_PER_PASS (16 * TI)     // 64
#define RG 5                        // 5*64 = 320 >= 272
#define ROWS_PER_BLOCK 272          // 37 * 272 = 10064 >= 10000
#define NBLK_ROWS 37
#define NBLK_J 4
#define STEPS (JT / 32)             // 80
#define DEPTH 4                     // software-pipeline depth (STEPS % DEPTH == 0)
#define SMEM_BYTES (JT * PITCH * 4) // 204800 B
#define GRID_MAIN (NBLK_J * NBLK_ROWS)  // 148

#define PBLOCKS 40

// Device-global scratch
__device__ double g_cut;
__device__ float  g_invg[KK];
__device__ float  g_ep;
__device__ float  g_part[PBLOCKS * 32];
__device__ unsigned int g_ctr_p;   // k_partial completion counter (self-resetting)
__device__ unsigned int g_ctr_m;   // k_main completion counter (self-resetting)

// ---- packed f32x2 helpers (Blackwell FFMA2) ----
__device__ __forceinline__ unsigned long long ffma2(unsigned long long a,
                                                    unsigned long long b,
                                                    unsigned long long c) {
    unsigned long long d;
    asm("fma.rn.f32x2 %0, %1, %2, %3;" : "=l"(d) : "l"(a), "l"(b), "l"(c));
    return d;
}
__device__ __forceinline__ unsigned long long pack2(float x, float y) {
    unsigned long long d;
    asm("mov.b64 %0, {%1, %2};" : "=l"(d) : "f"(x), "f"(y));
    return d;
}
__device__ __forceinline__ float2 unpack2(unsigned long long v) {
    float2 r;
    asm("mov.b64 {%0, %1}, %2;" : "=f"(r.x), "=f"(r.y) : "l"(v));
    return r;
}

// ============================================================
// Kernel 1: partials of gamma[k]=sum Y[i,k]*deg[i], colsum[k]=sum Y[i,k];
// last block finalizes: g_invg, g_ep, zeroes g_cut.
// ============================================================
__global__ void k_partial(const float* __restrict__ Y,
                          const float* __restrict__ deg) {
    int i = blockIdx.x * 256 + threadIdx.x;
    float g[KK], c[KK];
#pragma unroll
    for (int k = 0; k < KK; k++) { g[k] = 0.f; c[k] = 0.f; }

    if (i < NN) {
        float d = deg[i];
        const float4* yr = (const float4*)(Y + (size_t)i * KK);
#pragma unroll
        for (int q = 0; q < 4; q++) {
            float4 v = yr[q];
            c[q * 4 + 0] = v.x; c[q * 4 + 1] = v.y;
            c[q * 4 + 2] = v.z; c[q * 4 + 3] = v.w;
            g[q * 4 + 0] = v.x * d; g[q * 4 + 1] = v.y * d;
            g[q * 4 + 2] = v.z * d; g[q * 4 + 3] = v.w * d;
        }
    }
#pragma unroll
    for (int k = 0; k < KK; k++) {
#pragma unroll
        for (int o = 16; o; o >>= 1) {
            g[k] += __shfl_xor_sync(0xffffffffu, g[k], o);
            c[k] += __shfl_xor_sync(0xffffffffu, c[k], o);
        }
    }
    __shared__ float red[8][32];
    __shared__ bool  is_last;
    int warp = threadIdx.x >> 5, lane = threadIdx.x & 31;
    if (lane == 0) {
#pragma unroll
        for (int k = 0; k < KK; k++) {
            red[warp][k]      = g[k];
            red[warp][16 + k] = c[k];
        }
    }
    __syncthreads();
    if (threadIdx.x < 32) {
        float s = 0.f;
#pragma unroll
        for (int w = 0; w < 8; w++) s += red[w][threadIdx.x];
        g_part[blockIdx.x * 32 + threadIdx.x] = s;
    }
    // completion protocol
    __threadfence();
    if (threadIdx.x == 0) {
        unsigned int old = atomicAdd(&g_ctr_p, 1u);
        is_last = (old == PBLOCKS - 1);
    }
    __syncthreads();
    if (is_last && threadIdx.x < 32) {
        __threadfence();
        int t = threadIdx.x;
        const volatile float* gp = g_part;
        float s = 0.f;
        for (int b = 0; b < PBLOCKS; b++) s += gp[b * 32 + t];
        red[0][t] = s;
        __syncwarp();
        if (t < KK) g_invg[t] = 1.0f / s;
        if (t == 0) {
            float e = 0.f;
#pragma unroll
            for (int k = 0; k < KK; k++) {
                float d2 = red[0][16 + k] - MEAN_NODES;
                e += d2 * d2;
            }
            g_ep   = e;
            g_cut  = 0.0;
            g_ctr_p = 0u;   // reset for next launch
        }
    }
}

// ============================================================
// Kernel 2: main fused pass over A.
//   W tile: w_jk = 1 - Y[j,k]. acc_i[k] += A_ij * w_jk.
//   finalize: part += dot(Yn_i, acc_i). Last block writes output.
// ============================================================
extern __shared__ float sW[];

__global__ void __launch_bounds__(THREADS, 1)
k_main(const float* __restrict__ A, const float* __restrict__ Y,
       float* __restrict__ out) {
    const int jt = blockIdx.x;
    const int rb = blockIdx.y;
    const int j0 = jt * JT;
    const int jlim = NN - j0;   // valid local columns in this tile

    // Cooperative tile: w = 1 - Y[j0..j0+JT), pitch 20, zero-fill tail
    for (int idx = threadIdx.x; idx < JT * 4; idx += THREADS) {
        int r = idx >> 2, c = idx & 3;
        int j = j0 + r;
        float4 v = make_float4(0.f, 0.f, 0.f, 0.f);
        if (j < NN) {
            float4 y = *(const float4*)(Y + (size_t)j * KK + c * 4);
            v = make_float4(1.f - y.x, 1.f - y.y, 1.f - y.z, 1.f - y.w);
        }
        *(float4*)(sW + r * PITCH + c * 4) = v;
    }
    __syncthreads();

    const int warp = threadIdx.x >> 5;
    const int lane = threadIdx.x & 31;
    float part = 0.0f;

#pragma unroll 1
    for (int rg = 0; rg < RG; rg++) {
        const int li = rg * ROWS_PER_PASS + warp * TI;  // local row in block
        const int i0 = rb * ROWS_PER_BLOCK + li;        // global row
        if (li >= ROWS_PER_BLOCK || i0 >= NN) continue; // warp-uniform skip

        bool rvalid[TI];
        const float* aptr[TI];
        unsigned long long acc[TI][8];
#pragma unroll
        for (int r = 0; r < TI; r++) {
            rvalid[r] = (li + r) < ROWS_PER_BLOCK && (i0 + r) < NN;
            aptr[r]   = A + (size_t)(i0 + r) * NN + j0 + lane;
#pragma unroll
            for (int p = 0; p < 8; p++) acc[r][p] = 0ULL;
        }

        // ---- depth-4 software pipeline over 32-column steps ----
        float a[DEPTH][TI];
#pragma unroll
        for (int s = 0; s < DEPTH; s++) {
            const int  jj  = s * 32 + lane;
            const bool jok = jj < jlim;
#pragma unroll
            for (int r = 0; r < TI; r++)
                a[s][r] = (jok && rvalid[r]) ? __ldcs(aptr[r] + s * 32) : 0.f;
        }

#pragma unroll 4
        for (int step = 0; step < STEPS; step++) {
            const int buf = step & (DEPTH - 1);

            // prefetch step+DEPTH into the slot we're about to free
            {
                const int  jn   = (step + DEPTH) * 32 + lane;
                const bool jokn = (step + DEPTH < STEPS) && (jn < jlim);
                float an[TI];
#pragma unroll
                for (int r = 0; r < TI; r++)
                    an[r] = (jokn && rvalid[r])
                            ? __ldcs(aptr[r] + (step + DEPTH) * 32) : 0.f;

                // W[j, 0..15] as 8 packed f32x2 (conflict-free, pitch 20)
                const int jj = step * 32 + lane;
                const ulonglong2* yp = (const ulonglong2*)(sW + jj * PITCH);
                ulonglong2 y01 = yp[0], y23 = yp[1], y45 = yp[2], y67 = yp[3];

#pragma unroll
                for (int r = 0; r < TI; r++) {
                    unsigned long long ap = pack2(a[buf][r], a[buf][r]);
                    acc[r][0] = ffma2(ap, y01.x, acc[r][0]);
                    acc[r][1] = ffma2(ap, y01.y, acc[r][1]);
                    acc[r][2] = ffma2(ap, y23.x, acc[r][2]);
                    acc[r][3] = ffma2(ap, y23.y, acc[r][3]);
                    acc[r][4] = ffma2(ap, y45.x, acc[r][4]);
                    acc[r][5] = ffma2(ap, y45.y, acc[r][5]);
                    acc[r][6] = ffma2(ap, y67.x, acc[r][6]);
                    acc[r][7] = ffma2(ap, y67.y, acc[r][7]);
                }
#pragma unroll
                for (int r = 0; r < TI; r++) a[buf][r] = an[r];
            }
        }

        // finalize this pass
        float iv[KK];
#pragma unroll
        for (int k = 0; k < KK; k++) iv[k] = g_invg[k];

#pragma unroll
        for (int r = 0; r < TI; r++) {
            if (!rvalid[r]) continue;
            const float* yi = Y + (size_t)(i0 + r) * KK;
            float dot = 0.f;
#pragma unroll
            for (int p = 0; p < 8; p++) {
                float2 u = unpack2(acc[r][p]);
                dot += (yi[2 * p]     * iv[2 * p])     * u.x
                     + (yi[2 * p + 1] * iv[2 * p + 1]) * u.y;
            }
            part += dot;
        }
    }

    // warp reduce, one double atomic per warp
#pragma unroll
    for (int o = 16; o; o >>= 1) part += __shfl_xor_sync(0xffffffffu, part, o);
    if (lane == 0) atomicAdd(&g_cut, (double)part);

    // last-block writes the scalar output
    __shared__ bool is_last;
    __threadfence();
    __syncthreads();
    if (threadIdx.x == 0) {
        unsigned int old = atomicAdd(&g_ctr_m, 1u);
        is_last = (old == GRID_MAIN - 1);
    }
    __syncthreads();
    if (is_last && threadIdx.x == 0) {
        __threadfence();
        double cut = *((volatile double*)&g_cut);
        out[0] = (float)(cut + (double)g_ep);
        g_ctr_m = 0u;   // reset for next launch
    }
}

extern "C" void kernel_launch(void* const* d_in, const int* in_sizes, int n_in,
                              void* d_out, int out_size) {
    const float* Y   = (const float*)d_in[0];   // [N, K]
    const float* A   = (const float*)d_in[1];   // [N, N]
    const float* deg = (const float*)d_in[2];   // [N, 1]
    float* out = (float*)d_out;

    cudaFuncSetAttribute(k_main, cudaFuncAttributeMaxDynamicSharedMemorySize,
                         SMEM_BYTES);

    k_partial<<<PBLOCKS, 256>>>(Y, deg);
    dim3 grid(NBLK_J, NBLK_ROWS);
    k_main<<<grid, THREADS, SMEM_BYTES>>>(A, Y, out);
}